// round 4
// baseline (speedup 1.0000x reference)
#include <cuda_runtime.h>

#define NTOT 200      // histogram bins
#define TILE 256      // tile side (A rows and B cols per block)
#define BLKT 128      // threads per block (each thread owns 2 A rows)
#define NWARP 4

// 3 raw integer histograms: [0]=00-triangle, [1]=01-cross, [2]=11-triangle.
// Statically zeroed at load; finalize_kernel re-zeroes after each use so the
// graph replays always start clean.
__device__ int g_hist[3 * NTOT];

__device__ __forceinline__ float fsqrt_approx(float x) {
    float r;
    asm("sqrt.approx.f32 %0, %1;" : "=f"(r) : "f"(x));
    return r;
}

// Invert upper-triangle linear index t -> (bi, bj), bj >= bi, n tiles per side.
__device__ __forceinline__ void tri_decode(int t, int n, int& bi, int& bj) {
    float fn = (float)(2 * n + 1);
    int b = (int)((fn - sqrtf(fmaxf(fn * fn - 8.0f * (float)t, 0.0f))) * 0.5f);
    if (b < 0) b = 0;
    if (b > n - 1) b = n - 1;
    while (b > 0 && t < b * (2 * n - b + 1) / 2) b--;
    while (b < n - 1 && t >= (b + 1) * (2 * n - b) / 2) b++;
    bi = b;
    bj = b + (t - b * (2 * n - b + 1) / 2);
}

// One fused kernel: per-block on-the-fly scaling of raw positions (no prep
// pass), all three pair regions in one grid, 2 A-rows per thread so each
// LDS.128 broadcast of a B point serves 2 pairs.
__global__ __launch_bounds__(BLKT) void pair_fused_kernel(
    const float* __restrict__ pos0, const float* __restrict__ pos1,
    const float* __restrict__ rs,
    int n0, int n1, int nb0, int nb1, int T0, int C)
{
    __shared__ float4 sB[TILE];
    __shared__ int    sh[NWARP * NTOT];

    // ---- decode block -> work unit ----
    int w = blockIdx.x;
    int bi, bj, nA, nB, histIdx;
    const float *pA, *pB;
    bool diag;
    if (w < T0) {                     // 0-0 triangle
        tri_decode(w, nb0, bi, bj);
        pA = pos0; pB = pos0; nA = n0; nB = n0; histIdx = 0;
        diag = (bi == bj);
    } else if (w < T0 + C) {          // 0-1 cross
        int u = w - T0;
        bi = u / nb1; bj = u - bi * nb1;
        pA = pos0; nA = n0; pB = pos1; nB = n1; histIdx = 1;
        diag = false;
    } else {                          // 1-1 triangle
        int u = w - T0 - C;
        tri_decode(u, nb1, bi, bj);
        pA = pos1; pB = pos1; nA = n1; nB = n1; histIdx = 2;
        diag = (bi == bj);
    }
    const int rowStart  = bi * TILE;
    const int chunkBase = bj * TILE;
    const int tid = threadIdx.x;
    const int wid = tid >> 5;
    int* myh = &sh[wid * NTOT];

    #pragma unroll
    for (int idx = tid; idx < NWARP * NTOT; idx += BLKT) sh[idx] = 0;

    // prescale by INV_DELTA=20 so bin = floor(sqrt(d2)) directly
    const float r0 = rs[0] * 20.0f, r1 = rs[1] * 20.0f, r2 = rs[2] * 20.0f;

    // ---- B tile: scale 2 points per thread into smem ----
    #pragma unroll
    for (int t = 0; t < 2; t++) {
        int k = tid + t * BLKT;
        int j = chunkBase + k;
        float4 v = make_float4(0.f, 0.f, 0.f, 1e30f);
        if (j < nB) {
            float x = pB[j * 3 + 0] * r0;
            float y = pB[j * 3 + 1] * r1;
            float z = pB[j * 3 + 2] * r2;
            float q = x * x; q = fmaf(y, y, q); q = fmaf(z, z, q);
            v = make_float4(x, y, z, q);
        }
        sB[k] = v;
    }

    // ---- A rows: 2 per thread, kept in registers with -2 folded in ----
    float ax2[2], ay2[2], az2[2], aw[2];
    int   irow[2];
    #pragma unroll
    for (int t = 0; t < 2; t++) {
        int i = rowStart + tid + t * BLKT;
        irow[t] = i;
        float x = 0.f, y = 0.f, z = 0.f, q = 1e30f;
        if (i < nA) {
            x = pA[i * 3 + 0] * r0;
            y = pA[i * 3 + 1] * r1;
            z = pA[i * 3 + 2] * r2;
            q = x * x; q = fmaf(y, y, q); q = fmaf(z, z, q);
        }
        ax2[t] = -2.0f * x; ay2[t] = -2.0f * y; az2[t] = -2.0f * z; aw[t] = q;
    }
    __syncthreads();

    if (diag) {
        #pragma unroll 4
        for (int k = 0; k < TILE; k++) {
            float4 b = sB[k];
            #pragma unroll
            for (int t = 0; t < 2; t++) {
                float s = aw[t] + b.w;
                s = fmaf(ax2[t], b.x, s);
                s = fmaf(ay2[t], b.y, s);
                s = fmaf(az2[t], b.z, s);
                float d = fsqrt_approx(fmaxf(s, 0.0f));
                if (d < (float)NTOT && (chunkBase + k) > irow[t])
                    atomicAdd(&myh[(int)d], 1);
            }
        }
    } else {
        #pragma unroll 4
        for (int k = 0; k < TILE; k++) {
            float4 b = sB[k];
            #pragma unroll
            for (int t = 0; t < 2; t++) {
                float s = aw[t] + b.w;
                s = fmaf(ax2[t], b.x, s);
                s = fmaf(ay2[t], b.y, s);
                s = fmaf(az2[t], b.z, s);
                float d = fsqrt_approx(fmaxf(s, 0.0f));
                if (d < (float)NTOT)
                    atomicAdd(&myh[(int)d], 1);
            }
        }
    }
    __syncthreads();

    // FIX (R3 bug): tid only reaches BLKT-1=127, so bins 128..199 were never
    // flushed. Stride over all NTOT bins.
    for (int t = tid; t < NTOT; t += BLKT) {
        int v = sh[t] + sh[NTOT + t] + sh[2 * NTOT + t] + sh[3 * NTOT + t];
        if (v) atomicAdd(&g_hist[histIdx * NTOT + t], v);
    }
}

// Single block: normalize all 800 outputs, then zero g_hist for next replay.
__global__ void finalize_kernel(const float* __restrict__ count_in,
                                float* __restrict__ out,
                                const float* __restrict__ rs,
                                int n0, int n1)
{
    int idx = threadIdx.x;
    if (idx < 4 * NTOT) {
        int k  = idx % NTOT;
        int ij = idx / NTOT;                       // i*2 + j
        int histIdx = (ij == 0) ? 0 : ((ij == 3) ? 2 : 1);
        float mult  = (ij == 0 || ij == 3) ? 2.0f : 1.0f;  // triangle -> full
        float na = (float)((ij >> 1) ? n1 : n0);
        float nb = (float)((ij & 1) ? n1 : n0);
        float vol = rs[0] * rs[1] * rs[2];

        float counts = (float)g_hist[histIdx * NTOT + k] * mult;
        double r = 0.025 + (double)k * 0.05;
        float sv = (float)(r * 0.05 * 2.0 * 3.14159265358979323846 * 3.0);
        float density = nb / vol;
        float res = counts / density / sv / na;   // same division order as ref
        out[idx] = count_in[idx] + res;
    }
    __syncthreads();
    if (idx < 3 * NTOT) g_hist[idx] = 0;
}

extern "C" void kernel_launch(void* const* d_in, const int* in_sizes, int n_in,
                              void* d_out, int out_size)
{
    const float* pos0  = (const float*)d_in[0];
    const float* pos1  = (const float*)d_in[1];
    const float* count = (const float*)d_in[2];
    const float* rs    = (const float*)d_in[3];
    int n0 = in_sizes[0] / 3;
    int n1 = in_sizes[1] / 3;
    float* out = (float*)d_out;

    int nb0 = (n0 + TILE - 1) / TILE;
    int nb1 = (n1 + TILE - 1) / TILE;
    int T0 = nb0 * (nb0 + 1) / 2;
    int C  = nb0 * nb1;
    int T1 = nb1 * (nb1 + 1) / 2;
    pair_fused_kernel<<<T0 + C + T1, BLKT>>>(pos0, pos1, rs, n0, n1,
                                             nb0, nb1, T0, C);

    finalize_kernel<<<1, 4 * NTOT>>>(count, out, rs, n0, n1);
}